// round 1
// baseline (speedup 1.0000x reference)
#include <cuda_runtime.h>
#include <math.h>

// Problem constants (fixed shapes from reference)
#define B_   32
#define C_   256
#define H_   64
#define W_   64
#define HW_  (H_ * W_)          // 4096
#define BHW_ (B_ * HW_)         // 131072
#define EPS_ 1e-8f

// Scratch accumulators: [0] = sum(sim*mask), [1] = sum(mask)
__device__ float g_acc[2];

__global__ void cms_zero_kernel() {
    g_acc[0] = 0.0f;
    g_acc[1] = 0.0f;
}

__global__ __launch_bounds__(256)
void cms_main_kernel(const float* __restrict__ u,
                     const float* __restrict__ m,
                     const int*   __restrict__ mask) {
    const int idx = blockIdx.x * blockDim.x + threadIdx.x;   // 0..BHW_-1
    const int b  = idx >> 12;          // / HW_
    const int hw = idx & (HW_ - 1);    // % HW_

    const float* __restrict__ up = u + (size_t)b * C_ * HW_ + hw;
    const float* __restrict__ mp = m + (size_t)b * C_ * HW_ + hw;

    float dot = 0.0f, uu = 0.0f, mm = 0.0f;
    #pragma unroll 8
    for (int c = 0; c < C_; ++c) {
        float a = __ldg(up + (size_t)c * HW_);
        float x = __ldg(mp + (size_t)c * HW_);
        dot = fmaf(a, x, dot);
        uu  = fmaf(a, a, uu);
        mm  = fmaf(x, x, mm);
    }

    const float maskf = (mask[idx] != 0) ? 1.0f : 0.0f;
    const float denom = fmaxf(sqrtf(uu), EPS_) * fmaxf(sqrtf(mm), EPS_);
    float contrib = (dot / denom) * maskf;
    float msum = maskf;

    // Warp reduction
    #pragma unroll
    for (int off = 16; off > 0; off >>= 1) {
        contrib += __shfl_down_sync(0xFFFFFFFFu, contrib, off);
        msum    += __shfl_down_sync(0xFFFFFFFFu, msum, off);
    }

    // Block reduction across 8 warps
    __shared__ float s_c[8];
    __shared__ float s_m[8];
    const int lane = threadIdx.x & 31;
    const int warp = threadIdx.x >> 5;
    if (lane == 0) { s_c[warp] = contrib; s_m[warp] = msum; }
    __syncthreads();
    if (warp == 0) {
        float bc = (lane < 8) ? s_c[lane] : 0.0f;
        float bm = (lane < 8) ? s_m[lane] : 0.0f;
        #pragma unroll
        for (int off = 4; off > 0; off >>= 1) {
            bc += __shfl_down_sync(0xFFFFFFFFu, bc, off);
            bm += __shfl_down_sync(0xFFFFFFFFu, bm, off);
        }
        if (lane == 0) {
            atomicAdd(&g_acc[0], bc);
            atomicAdd(&g_acc[1], bm);
        }
    }
}

__global__ void cms_finalize_kernel(float* __restrict__ out) {
    out[0] = g_acc[0] / g_acc[1];
}

extern "C" void kernel_launch(void* const* d_in, const int* in_sizes, int n_in,
                              void* d_out, int out_size) {
    const float* u    = (const float*)d_in[0];  // unmasked_latent_tensors [B,C,H,W]
    const float* m    = (const float*)d_in[1];  // masked_latent_tensors   [B,C,H,W]
    const int*   mask = (const int*)d_in[2];    // latent_mask [B,H,W]
    float* out = (float*)d_out;

    cms_zero_kernel<<<1, 1>>>();
    cms_main_kernel<<<BHW_ / 256, 256>>>(u, m, mask);
    cms_finalize_kernel<<<1, 1>>>(out);
}